// round 2
// baseline (speedup 1.0000x reference)
#include <cuda_runtime.h>
#include <cstdint>

#define FEAT   128
#define HID    128
#define HID2   64
#define BM     128
#define THREADS 256
#define PITCH  132     // h1 row pitch in floats (16B aligned, 4-bank stagger per row)
#define MAXN   10000

__device__ __align__(16) float g_Pdrug[MAXN * HID];
__device__ __align__(16) float g_Pdis [MAXN * HID];

__device__ __forceinline__ float gelu_exact(float x) {
    return 0.5f * x * (1.0f + erff(x * 0.70710678118654752440f));
}

// ---------------------------------------------------------------------------
// Precompute P = feat @ W1_slice for both tables (blockIdx.y selects table).
// ---------------------------------------------------------------------------
__global__ __launch_bounds__(THREADS) void precompute_kernel(
    const float* __restrict__ drug, const float* __restrict__ dis,
    const float* __restrict__ W1, int n_drug, int n_dis)
{
    const int table = blockIdx.y;
    const int n = table ? n_dis : n_drug;
    const float* __restrict__ feat = table ? dis : drug;
    const float* __restrict__ w    = W1 + (table ? (size_t)FEAT * HID : 0);
    float* __restrict__ outp       = table ? g_Pdis : g_Pdrug;

    const int n0 = blockIdx.x * 32;
    if (n0 >= n) return;

    __shared__ float fs[32][FEAT];
    const int tid = threadIdx.x;
    for (int idx = tid; idx < 32 * FEAT; idx += THREADS) {
        int node = idx >> 7, k = idx & 127;
        fs[node][k] = (n0 + node < n) ? feat[(size_t)(n0 + node) * FEAT + k] : 0.0f;
    }
    __syncthreads();

    const int tx = tid & 31, ty = tid >> 5;
    float acc[4][4] = {};
    #pragma unroll 4
    for (int k = 0; k < FEAT; ++k) {
        float wv[4];
        #pragma unroll
        for (int c = 0; c < 4; ++c) wv[c] = w[(size_t)k * HID + tx + 32 * c];
        #pragma unroll
        for (int i = 0; i < 4; ++i) {
            float f = fs[ty * 4 + i][k];
            #pragma unroll
            for (int c = 0; c < 4; ++c) acc[i][c] = fmaf(f, wv[c], acc[i][c]);
        }
    }
    #pragma unroll
    for (int i = 0; i < 4; ++i) {
        int node = n0 + ty * 4 + i;
        if (node < n) {
            #pragma unroll
            for (int c = 0; c < 4; ++c)
                outp[(size_t)node * HID + tx + 32 * c] = acc[i][c];
        }
    }
}

// ---------------------------------------------------------------------------
// Fused per-edge kernel: 128 edges / block.
// ---------------------------------------------------------------------------
extern __shared__ float smem[];

__global__ __launch_bounds__(THREADS, 2) void edge_kernel(
    const int* __restrict__ src, const int* __restrict__ dst,
    const float* __restrict__ b1, const float* __restrict__ g1, const float* __restrict__ be1,
    const float* __restrict__ W2, const float* __restrict__ b2,
    const float* __restrict__ g2, const float* __restrict__ be2,
    const float* __restrict__ W3, const float* __restrict__ b3,
    float* __restrict__ out, int E)
{
    float* h1s  = smem;                    // BM * PITCH
    float* w2s  = smem + BM * PITCH;       // HID * HID2
    float* w3s  = w2s + HID * HID2;
    float* b1s  = w3s + HID2;
    float* g1s  = b1s + HID;
    float* be1s = g1s + HID;
    float* b2s  = be1s + HID;
    float* g2s  = b2s + HID2;
    float* be2s = g2s + HID2;

    const int tid = threadIdx.x;
    for (int i = tid; i < HID * HID2; i += THREADS) w2s[i] = W2[i];
    if (tid < HID)  { b1s[tid] = b1[tid]; g1s[tid] = g1[tid]; be1s[tid] = be1[tid]; }
    if (tid < HID2) { w3s[tid] = W3[tid]; b2s[tid] = b2[tid]; g2s[tid] = g2[tid]; be2s[tid] = be2[tid]; }
    __syncthreads();

    const int e0 = blockIdx.x * BM;
    const int warp = tid >> 5, lane = tid & 31;

    // ---------------- Phase 1: z1 = Pdrug[s] + Pdis[d] + b1 ; LN ; GELU ----
    for (int er = warp; er < BM; er += 8) {
        const int e = e0 + er;
        if (e < E) {
            const int s = src[e], d = dst[e];
            const float4 a  = reinterpret_cast<const float4*>(g_Pdrug + (size_t)s * HID)[lane];
            const float4 bq = reinterpret_cast<const float4*>(g_Pdis  + (size_t)d * HID)[lane];
            const float4 bb = reinterpret_cast<const float4*>(b1s)[lane];
            float v[4];
            v[0] = a.x + bq.x + bb.x;
            v[1] = a.y + bq.y + bb.y;
            v[2] = a.z + bq.z + bb.z;
            v[3] = a.w + bq.w + bb.w;
            float s1 = v[0] + v[1] + v[2] + v[3];
            float s2 = v[0]*v[0] + v[1]*v[1] + v[2]*v[2] + v[3]*v[3];
            #pragma unroll
            for (int m = 16; m > 0; m >>= 1) {
                s1 += __shfl_xor_sync(0xffffffffu, s1, m);
                s2 += __shfl_xor_sync(0xffffffffu, s2, m);
            }
            const float mu  = s1 * (1.0f / HID);
            const float var = s2 * (1.0f / HID) - mu * mu;
            const float rs  = rsqrtf(var + 1e-5f);
            const float4 gg = reinterpret_cast<const float4*>(g1s)[lane];
            const float4 ee = reinterpret_cast<const float4*>(be1s)[lane];
            float4 hv;
            hv.x = gelu_exact((v[0] - mu) * rs * gg.x + ee.x);
            hv.y = gelu_exact((v[1] - mu) * rs * gg.y + ee.y);
            hv.z = gelu_exact((v[2] - mu) * rs * gg.z + ee.z);
            hv.w = gelu_exact((v[3] - mu) * rs * gg.w + ee.w);
            reinterpret_cast<float4*>(h1s + er * PITCH)[lane] = hv;
        } else {
            float4 z = {0.f, 0.f, 0.f, 0.f};
            reinterpret_cast<float4*>(h1s + er * PITCH)[lane] = z;
        }
    }
    __syncthreads();

    // ---------------- Phase 2: GEMM2, k-chunked vector LDS + f32x2 FMA -----
    const int tx = tid & 7, ty = tid >> 3;     // tx -> 8 cols, ty -> 4 rows
    const int r0 = ty * 4, c0 = tx * 8;
    unsigned long long acc[4][4];
    #pragma unroll
    for (int i = 0; i < 4; ++i)
        #pragma unroll
        for (int p = 0; p < 4; ++p) acc[i][p] = 0ull;

    const ulonglong2* __restrict__ w2v = reinterpret_cast<const ulonglong2*>(w2s);
    const float4* __restrict__ h1r0 = reinterpret_cast<const float4*>(h1s + (r0 + 0) * PITCH);
    const float4* __restrict__ h1r1 = reinterpret_cast<const float4*>(h1s + (r0 + 1) * PITCH);
    const float4* __restrict__ h1r2 = reinterpret_cast<const float4*>(h1s + (r0 + 2) * PITCH);
    const float4* __restrict__ h1r3 = reinterpret_cast<const float4*>(h1s + (r0 + 3) * PITCH);

    #pragma unroll 2
    for (int k0 = 0; k0 < HID; k0 += 4) {
        const int kq = k0 >> 2;
        float4 av[4];
        av[0] = h1r0[kq];
        av[1] = h1r1[kq];
        av[2] = h1r2[kq];
        av[3] = h1r3[kq];

        #pragma unroll
        for (int kk = 0; kk < 4; ++kk) {
            const int vb = ((k0 + kk) * HID2 + c0) >> 2;
            const ulonglong2 bw0 = w2v[vb];
            const ulonglong2 bw1 = w2v[vb + 1];
            const unsigned long long bw[4] = {bw0.x, bw0.y, bw1.x, bw1.y};
            #pragma unroll
            for (int i = 0; i < 4; ++i) {
                const float as = (kk == 0) ? av[i].x : (kk == 1) ? av[i].y
                               : (kk == 2) ? av[i].z : av[i].w;
                unsigned long long ap;
                asm("mov.b64 %0, {%1, %1};" : "=l"(ap) : "r"(__float_as_uint(as)));
                #pragma unroll
                for (int p = 0; p < 4; ++p)
                    asm("fma.rn.f32x2 %0, %1, %2, %0;" : "+l"(acc[i][p]) : "l"(ap), "l"(bw[p]));
            }
        }
    }

    // ---------------- Phase 3: +b2 ; LN(64) ; GELU ; dot(W3) + b3 ----------
    float w3r[8], g2r[8], be2r[8], b2r[8];
    #pragma unroll
    for (int cc = 0; cc < 8; ++cc) {
        w3r[cc] = w3s[c0 + cc]; g2r[cc] = g2s[c0 + cc];
        be2r[cc] = be2s[c0 + cc]; b2r[cc] = b2s[c0 + cc];
    }
    const float b3v = b3[0];

    #pragma unroll
    for (int i = 0; i < 4; ++i) {
        float z[8];
        #pragma unroll
        for (int p = 0; p < 4; ++p) {
            unsigned int lo, hi;
            asm("mov.b64 {%0, %1}, %2;" : "=r"(lo), "=r"(hi) : "l"(acc[i][p]));
            z[2 * p]     = __uint_as_float(lo) + b2r[2 * p];
            z[2 * p + 1] = __uint_as_float(hi) + b2r[2 * p + 1];
        }
        float s1 = 0.f, s2 = 0.f;
        #pragma unroll
        for (int cc = 0; cc < 8; ++cc) { s1 += z[cc]; s2 += z[cc] * z[cc]; }
        #pragma unroll
        for (int m = 4; m > 0; m >>= 1) {
            s1 += __shfl_xor_sync(0xffffffffu, s1, m);
            s2 += __shfl_xor_sync(0xffffffffu, s2, m);
        }
        const float mu  = s1 * (1.0f / HID2);
        const float var = s2 * (1.0f / HID2) - mu * mu;
        const float rs  = rsqrtf(var + 1e-5f);
        float dot = 0.f;
        #pragma unroll
        for (int cc = 0; cc < 8; ++cc) {
            float t = (z[cc] - mu) * rs * g2r[cc] + be2r[cc];
            dot = fmaf(gelu_exact(t), w3r[cc], dot);
        }
        #pragma unroll
        for (int m = 4; m > 0; m >>= 1)
            dot += __shfl_xor_sync(0xffffffffu, dot, m);
        const int e = e0 + r0 + i;
        if (tx == 0 && e < E) out[e] = dot + b3v;
    }
}

// ---------------------------------------------------------------------------
extern "C" void kernel_launch(void* const* d_in, const int* in_sizes, int n_in,
                              void* d_out, int out_size)
{
    const float* drug = (const float*)d_in[0];
    const float* dis  = (const float*)d_in[1];
    const int*   src  = (const int*)  d_in[2];
    const int*   dst  = (const int*)  d_in[3];
    const float* W1   = (const float*)d_in[4];
    const float* b1   = (const float*)d_in[5];
    const float* g1   = (const float*)d_in[6];
    const float* be1  = (const float*)d_in[7];
    const float* W2   = (const float*)d_in[8];
    const float* b2   = (const float*)d_in[9];
    const float* g2   = (const float*)d_in[10];
    const float* be2  = (const float*)d_in[11];
    const float* W3   = (const float*)d_in[12];
    const float* b3   = (const float*)d_in[13];
    float* out = (float*)d_out;

    const int n_drug = in_sizes[0] / FEAT;
    const int n_dis  = in_sizes[1] / FEAT;
    const int E      = in_sizes[2];

    const int nmax = n_drug > n_dis ? n_drug : n_dis;
    dim3 pgrid((nmax + 31) / 32, 2);
    precompute_kernel<<<pgrid, THREADS>>>(drug, dis, W1, n_drug, n_dis);

    const size_t SMEM_BYTES =
        (size_t)(BM * PITCH + HID * HID2 + HID2 + 3 * HID + 3 * HID2) * sizeof(float);
    cudaFuncSetAttribute(edge_kernel, cudaFuncAttributeMaxDynamicSharedMemorySize,
                         (int)SMEM_BYTES);
    const int blocks = (E + BM - 1) / BM;
    edge_kernel<<<blocks, THREADS, SMEM_BYTES>>>(
        src, dst, b1, g1, be1, W2, b2, g2, be2, W3, b3, out, E);
}

// round 4
// speedup vs baseline: 2.0723x; 2.0723x over previous
#include <cuda_runtime.h>
#include <cuda_fp16.h>
#include <cstdint>

#define FEAT   128
#define HID    128
#define HID2   64
#define BM     128
#define THREADS 256
#define MAXN   10000
#define APITCH 136            // halves per row (272B): 8-row groups hit distinct banks

// smem halves layout
#define SM_A    0                         // 128 x 136 fp16  (34816 B)
#define SM_B    (128 * APITCH * 2)        // 64 x 136 fp16   (17408 B) -> 34816
#define SM_PAR  (SM_B + 64 * APITCH * 2)  // 52224, 16B aligned
#define SM_B1   SM_PAR
#define SM_G1   (SM_B1 + 512)
#define SM_BE1  (SM_G1 + 512)
#define SM_B2   (SM_BE1 + 512)
#define SM_G2   (SM_B2 + 256)
#define SM_BE2  (SM_G2 + 256)
#define SM_W3   (SM_BE2 + 256)
#define SM_TOTAL (SM_W3 + 256)            // 54784 B

__device__ __align__(16) float g_Pdrug[MAXN * HID];
__device__ __align__(16) float g_Pdis [MAXN * HID];

__device__ __forceinline__ float gelu_exact(float x) {
    return 0.5f * x * (1.0f + erff(x * 0.70710678118654752440f));
}

// ---------------------------------------------------------------------------
__global__ __launch_bounds__(THREADS) void precompute_kernel(
    const float* __restrict__ drug, const float* __restrict__ dis,
    const float* __restrict__ W1, int n_drug, int n_dis)
{
    const int table = blockIdx.y;
    const int n = table ? n_dis : n_drug;
    const float* __restrict__ feat = table ? dis : drug;
    const float* __restrict__ w    = W1 + (table ? (size_t)FEAT * HID : 0);
    float* __restrict__ outp       = table ? g_Pdis : g_Pdrug;

    const int n0 = blockIdx.x * 32;
    if (n0 >= n) return;

    __shared__ float fs[32][FEAT];
    const int tid = threadIdx.x;
    for (int idx = tid; idx < 32 * FEAT; idx += THREADS) {
        int node = idx >> 7, k = idx & 127;
        fs[node][k] = (n0 + node < n) ? feat[(size_t)(n0 + node) * FEAT + k] : 0.0f;
    }
    __syncthreads();

    const int tx = tid & 31, ty = tid >> 5;
    float acc[4][4] = {};
    #pragma unroll 4
    for (int k = 0; k < FEAT; ++k) {
        float wv[4];
        #pragma unroll
        for (int c = 0; c < 4; ++c) wv[c] = w[(size_t)k * HID + tx + 32 * c];
        #pragma unroll
        for (int i = 0; i < 4; ++i) {
            float f = fs[ty * 4 + i][k];
            #pragma unroll
            for (int c = 0; c < 4; ++c) acc[i][c] = fmaf(f, wv[c], acc[i][c]);
        }
    }
    #pragma unroll
    for (int i = 0; i < 4; ++i) {
        int node = n0 + ty * 4 + i;
        if (node < n) {
            #pragma unroll
            for (int c = 0; c < 4; ++c)
                outp[(size_t)node * HID + tx + 32 * c] = acc[i][c];
        }
    }
}

// ---------------------------------------------------------------------------
// Fused edge kernel. Phase 1: gather + LN + GELU -> fp16 A tile.
// Phase 2: HMMA m16n8k16 (fp16 in, fp32 accum). Phase 3: LN(64)+GELU+dot.
// ---------------------------------------------------------------------------
extern __shared__ char smem_raw[];

__global__ __launch_bounds__(THREADS, 2) void edge_kernel(
    const int* __restrict__ src, const int* __restrict__ dst,
    const float* __restrict__ b1, const float* __restrict__ g1, const float* __restrict__ be1,
    const float* __restrict__ W2, const float* __restrict__ b2,
    const float* __restrict__ g2, const float* __restrict__ be2,
    const float* __restrict__ W3, const float* __restrict__ b3,
    float* __restrict__ out, int E)
{
    __half* As = (__half*)(smem_raw + SM_A);
    __half* Bs = (__half*)(smem_raw + SM_B);
    float* b1s  = (float*)(smem_raw + SM_B1);
    float* g1s  = (float*)(smem_raw + SM_G1);
    float* be1s = (float*)(smem_raw + SM_BE1);
    float* b2s  = (float*)(smem_raw + SM_B2);
    float* g2s  = (float*)(smem_raw + SM_G2);
    float* be2s = (float*)(smem_raw + SM_BE2);
    float* w3s  = (float*)(smem_raw + SM_W3);

    const int tid = threadIdx.x;
    const int wid = tid >> 5, lane = tid & 31;

    if (tid < HID)  { b1s[tid] = b1[tid]; g1s[tid] = g1[tid]; be1s[tid] = be1[tid]; }
    if (tid < HID2) { b2s[tid] = b2[tid]; g2s[tid] = g2[tid]; be2s[tid] = be2[tid]; w3s[tid] = W3[tid]; }

    // B tile: W2 [k=128][n=64] gmem row-major -> Bs[n][k] fp16 (col-major B)
    for (int i = tid; i < HID * HID2; i += THREADS) {
        int k = i >> 6, n = i & 63;
        Bs[n * APITCH + k] = __float2half_rn(W2[i]);
    }
    __syncthreads();

    const int e0 = blockIdx.x * BM;

    // ---------------- Phase 1: z1 = Pdrug[s]+Pdis[d]+b1 ; LN ; GELU -> fp16 A
    for (int er = wid; er < BM; er += 8) {
        const int e = e0 + er;
        uint2* dstp = (uint2*)(As + er * APITCH + lane * 4);
        if (e < E) {
            const int s = src[e], d = dst[e];
            const float4 a  = reinterpret_cast<const float4*>(g_Pdrug + (size_t)s * HID)[lane];
            const float4 bq = reinterpret_cast<const float4*>(g_Pdis  + (size_t)d * HID)[lane];
            const float4 bb = reinterpret_cast<const float4*>(b1s)[lane];
            float v[4];
            v[0] = a.x + bq.x + bb.x;
            v[1] = a.y + bq.y + bb.y;
            v[2] = a.z + bq.z + bb.z;
            v[3] = a.w + bq.w + bb.w;
            float s1 = v[0] + v[1] + v[2] + v[3];
            float s2 = v[0]*v[0] + v[1]*v[1] + v[2]*v[2] + v[3]*v[3];
            #pragma unroll
            for (int m = 16; m > 0; m >>= 1) {
                s1 += __shfl_xor_sync(0xffffffffu, s1, m);
                s2 += __shfl_xor_sync(0xffffffffu, s2, m);
            }
            const float mu  = s1 * (1.0f / HID);
            const float var = s2 * (1.0f / HID) - mu * mu;
            const float rs  = rsqrtf(var + 1e-5f);
            const float4 gg = reinterpret_cast<const float4*>(g1s)[lane];
            const float4 ee = reinterpret_cast<const float4*>(be1s)[lane];
            float h0 = gelu_exact((v[0] - mu) * rs * gg.x + ee.x);
            float h1 = gelu_exact((v[1] - mu) * rs * gg.y + ee.y);
            float h2 = gelu_exact((v[2] - mu) * rs * gg.z + ee.z);
            float h3 = gelu_exact((v[3] - mu) * rs * gg.w + ee.w);
            __half2 p0 = __floats2half2_rn(h0, h1);
            __half2 p1 = __floats2half2_rn(h2, h3);
            uint2 pk;
            pk.x = *reinterpret_cast<uint32_t*>(&p0);
            pk.y = *reinterpret_cast<uint32_t*>(&p1);
            *dstp = pk;
        } else {
            uint2 z = {0u, 0u};
            *dstp = z;
        }
    }
    __syncthreads();

    // ---------------- Phase 2: HMMA m16n8k16, warp computes 16 rows x 64 cols
    const int r0  = wid * 16;
    const int gid = lane >> 2, tig = lane & 3;

    float acc[8][4];
    #pragma unroll
    for (int nt = 0; nt < 8; ++nt)
        #pragma unroll
        for (int j = 0; j < 4; ++j) acc[nt][j] = 0.0f;

    #pragma unroll
    for (int kt = 0; kt < 8; ++kt) {
        const int k0 = kt * 16;
        const uint32_t* arow0 = (const uint32_t*)(As + (r0 + gid) * APITCH + k0);
        const uint32_t* arow8 = (const uint32_t*)(As + (r0 + gid + 8) * APITCH + k0);
        uint32_t a0 = arow0[tig];
        uint32_t a1 = arow8[tig];
        uint32_t a2 = arow0[tig + 4];
        uint32_t a3 = arow8[tig + 4];
        #pragma unroll
        for (int nt = 0; nt < 8; ++nt) {
            const uint32_t* brow = (const uint32_t*)(Bs + (nt * 8 + gid) * APITCH + k0);
            uint32_t bb0 = brow[tig];
            uint32_t bb1 = brow[tig + 4];
            asm volatile(
                "mma.sync.aligned.m16n8k16.row.col.f32.f16.f16.f32 "
                "{%0,%1,%2,%3}, {%4,%5,%6,%7}, {%8,%9}, {%0,%1,%2,%3};"
                : "+f"(acc[nt][0]), "+f"(acc[nt][1]), "+f"(acc[nt][2]), "+f"(acc[nt][3])
                : "r"(a0), "r"(a1), "r"(a2), "r"(a3), "r"(bb0), "r"(bb1));
        }
    }

    // ---------------- Phase 3: +b2 ; LN(64) ; GELU ; dot(W3)+b3 ------------
    // Lane holds rows (r0+gid) and (r0+gid+8); cols nt*8 + 2*tig + {0,1}.
    float zA[16], zB[16];
    float s1a = 0.f, s2a = 0.f, s1b = 0.f, s2b = 0.f;
    #pragma unroll
    for (int nt = 0; nt < 8; ++nt) {
        #pragma unroll
        for (int j = 0; j < 2; ++j) {
            const int col = nt * 8 + 2 * tig + j;
            const float bb = b2s[col];
            const float tA = acc[nt][j]     + bb;
            const float tB = acc[nt][2 + j] + bb;
            zA[nt * 2 + j] = tA;
            zB[nt * 2 + j] = tB;
            s1a += tA; s2a += tA * tA;
            s1b += tB; s2b += tB * tB;
        }
    }
    #pragma unroll
    for (int m = 1; m <= 2; m <<= 1) {
        s1a += __shfl_xor_sync(0xffffffffu, s1a, m);
        s2a += __shfl_xor_sync(0xffffffffu, s2a, m);
        s1b += __shfl_xor_sync(0xffffffffu, s1b, m);
        s2b += __shfl_xor_sync(0xffffffffu, s2b, m);
    }
    const float muA = s1a * (1.0f / HID2);
    const float rsA = rsqrtf(s2a * (1.0f / HID2) - muA * muA + 1e-5f);
    const float muB = s1b * (1.0f / HID2);
    const float rsB = rsqrtf(s2b * (1.0f / HID2) - muB * muB + 1e-5f);

    float dotA = 0.f, dotB = 0.f;
    #pragma unroll
    for (int nt = 0; nt < 8; ++nt) {
        #pragma unroll
        for (int j = 0; j < 2; ++j) {
            const int col = nt * 8 + 2 * tig + j;
            const float gg = g2s[col], be = be2s[col], ww = w3s[col];
            dotA = fmaf(gelu_exact((zA[nt*2+j] - muA) * rsA * gg + be), ww, dotA);
            dotB = fmaf(gelu_exact((zB[nt*2+j] - muB) * rsB * gg + be), ww, dotB);
        }
    }
    #pragma unroll
    for (int m = 1; m <= 2; m <<= 1) {
        dotA += __shfl_xor_sync(0xffffffffu, dotA, m);
        dotB += __shfl_xor_sync(0xffffffffu, dotB, m);
    }

    if (tig == 0) {
        const float b3v = b3[0];
        const int eA = e0 + r0 + gid;
        const int eB = eA + 8;
        if (eA < E) out[eA] = dotA + b3v;
        if (eB < E) out[eB] = dotB + b3v;
    }
}

// ---------------------------------------------------------------------------
extern "C" void kernel_launch(void* const* d_in, const int* in_sizes, int n_in,
                              void* d_out, int out_size)
{
    const float* drug = (const float*)d_in[0];
    const float* dis  = (const float*)d_in[1];
    const int*   src  = (const int*)  d_in[2];
    const int*   dst  = (const int*)  d_in[3];
    const float* W1   = (const float*)d_in[4];
    const float* b1   = (const float*)d_in[5];
    const float* g1   = (const float*)d_in[6];
    const float* be1  = (const float*)d_in[7];
    const float* W2   = (const float*)d_in[8];
    const float* b2   = (const float*)d_in[9];
    const float* g2   = (const float*)d_in[10];
    const float* be2  = (const float*)d_in[11];
    const float* W3   = (const float*)d_in[12];
    const float* b3   = (const float*)d_in[13];
    float* out = (float*)d_out;

    const int n_drug = in_sizes[0] / FEAT;
    const int n_dis  = in_sizes[1] / FEAT;
    const int E      = in_sizes[2];

    const int nmax = n_drug > n_dis ? n_drug : n_dis;
    dim3 pgrid((nmax + 31) / 32, 2);
    precompute_kernel<<<pgrid, THREADS>>>(drug, dis, W1, n_drug, n_dis);

    cudaFuncSetAttribute(edge_kernel, cudaFuncAttributeMaxDynamicSharedMemorySize, SM_TOTAL);
    const int blocks = (E + BM - 1) / BM;
    edge_kernel<<<blocks, THREADS, SM_TOTAL>>>(
        src, dst, b1, g1, be1, W2, b2, g2, be2, W3, b3, out, E);
}

// round 5
// speedup vs baseline: 2.6423x; 1.2750x over previous
#include <cuda_runtime.h>
#include <cuda_fp16.h>
#include <cstdint>

#define FEAT   128
#define HID    128
#define HID2   64
#define BM     128
#define THREADS 256
#define MAXN   10000
#define APITCH 136            // halves per row (272B): 8-row groups hit distinct banks

// smem halves layout
#define SM_A    0                         // 128 x 136 fp16  (34816 B)
#define SM_B    (128 * APITCH * 2)        // 64 x 136 fp16   (17408 B)
#define SM_PAR  (SM_B + 64 * APITCH * 2)
#define SM_B1   SM_PAR
#define SM_G1   (SM_B1 + 512)
#define SM_BE1  (SM_G1 + 512)
#define SM_B2   (SM_BE1 + 512)
#define SM_G2   (SM_B2 + 256)
#define SM_BE2  (SM_G2 + 256)
#define SM_W3   (SM_BE2 + 256)
#define SM_TOTAL (SM_W3 + 256)            // 54784 B

__device__ __align__(16) float g_Pdrug[MAXN * HID];
__device__ __align__(16) float g_Pdis [MAXN * HID];

// tanh-form GELU with hardware MUFU tanh: ~5 FMA + 1 MUFU
__device__ __forceinline__ float gelu_fast(float x) {
    const float x2 = x * x;
    const float inner = x * fmaf(0.0356774081f, x2, 0.7978845608f);
    float t;
    asm("tanh.approx.f32 %0, %1;" : "=f"(t) : "f"(inner));
    return 0.5f * x * (1.0f + t);
}

// ---------------------------------------------------------------------------
__global__ __launch_bounds__(THREADS) void precompute_kernel(
    const float* __restrict__ drug, const float* __restrict__ dis,
    const float* __restrict__ W1, int n_drug, int n_dis)
{
    const int table = blockIdx.y;
    const int n = table ? n_dis : n_drug;
    const float* __restrict__ feat = table ? dis : drug;
    const float* __restrict__ w    = W1 + (table ? (size_t)FEAT * HID : 0);
    float* __restrict__ outp       = table ? g_Pdis : g_Pdrug;

    const int n0 = blockIdx.x * 32;
    if (n0 >= n) return;

    __shared__ float fs[32][FEAT];
    const int tid = threadIdx.x;
    for (int idx = tid; idx < 32 * FEAT; idx += THREADS) {
        int node = idx >> 7, k = idx & 127;
        fs[node][k] = (n0 + node < n) ? feat[(size_t)(n0 + node) * FEAT + k] : 0.0f;
    }
    __syncthreads();

    const int tx = tid & 31, ty = tid >> 5;
    float acc[4][4] = {};
    #pragma unroll 4
    for (int k = 0; k < FEAT; ++k) {
        float wv[4];
        #pragma unroll
        for (int c = 0; c < 4; ++c) wv[c] = w[(size_t)k * HID + tx + 32 * c];
        #pragma unroll
        for (int i = 0; i < 4; ++i) {
            float f = fs[ty * 4 + i][k];
            #pragma unroll
            for (int c = 0; c < 4; ++c) acc[i][c] = fmaf(f, wv[c], acc[i][c]);
        }
    }
    #pragma unroll
    for (int i = 0; i < 4; ++i) {
        int node = n0 + ty * 4 + i;
        if (node < n) {
            #pragma unroll
            for (int c = 0; c < 4; ++c)
                outp[(size_t)node * HID + tx + 32 * c] = acc[i][c];
        }
    }
}

// ---------------------------------------------------------------------------
extern __shared__ char smem_raw[];

__global__ __launch_bounds__(THREADS, 2) void edge_kernel(
    const int* __restrict__ src, const int* __restrict__ dst,
    const float* __restrict__ b1, const float* __restrict__ g1, const float* __restrict__ be1,
    const float* __restrict__ W2, const float* __restrict__ b2,
    const float* __restrict__ g2, const float* __restrict__ be2,
    const float* __restrict__ W3, const float* __restrict__ b3,
    float* __restrict__ out, int E)
{
    __half* As = (__half*)(smem_raw + SM_A);
    __half* Bs = (__half*)(smem_raw + SM_B);
    float* b1s  = (float*)(smem_raw + SM_B1);
    float* g1s  = (float*)(smem_raw + SM_G1);
    float* be1s = (float*)(smem_raw + SM_BE1);
    float* b2s  = (float*)(smem_raw + SM_B2);
    float* g2s  = (float*)(smem_raw + SM_G2);
    float* be2s = (float*)(smem_raw + SM_BE2);
    float* w3s  = (float*)(smem_raw + SM_W3);

    const int tid = threadIdx.x;
    const int wid = tid >> 5, lane = tid & 31;

    if (tid < HID)  { b1s[tid] = b1[tid]; g1s[tid] = g1[tid]; be1s[tid] = be1[tid]; }
    if (tid < HID2) { b2s[tid] = b2[tid]; g2s[tid] = g2[tid]; be2s[tid] = be2[tid]; w3s[tid] = W3[tid]; }

    // B tile: W2 [k=128][n=64] gmem row-major -> Bs[n][k] fp16 (col-major B)
    for (int i = tid; i < HID * HID2; i += THREADS) {
        int k = i >> 6, n = i & 63;
        Bs[n * APITCH + k] = __float2half_rn(W2[i]);
    }
    __syncthreads();

    const int e0 = blockIdx.x * BM;

    // ---------------- Phase 1: z1 = Pdrug[s]+Pdis[d]+b1 ; LN ; GELU -> fp16 A
    for (int er = wid; er < BM; er += 8) {
        const int e = e0 + er;
        uint2* dstp = (uint2*)(As + er * APITCH + lane * 4);
        if (e < E) {
            const int s = src[e], d = dst[e];
            const float4 a  = reinterpret_cast<const float4*>(g_Pdrug + (size_t)s * HID)[lane];
            const float4 bq = reinterpret_cast<const float4*>(g_Pdis  + (size_t)d * HID)[lane];
            const float4 bb = reinterpret_cast<const float4*>(b1s)[lane];
            float v[4];
            v[0] = a.x + bq.x + bb.x;
            v[1] = a.y + bq.y + bb.y;
            v[2] = a.z + bq.z + bb.z;
            v[3] = a.w + bq.w + bb.w;
            float s1 = v[0] + v[1] + v[2] + v[3];
            float s2 = v[0]*v[0] + v[1]*v[1] + v[2]*v[2] + v[3]*v[3];
            #pragma unroll
            for (int m = 16; m > 0; m >>= 1) {
                s1 += __shfl_xor_sync(0xffffffffu, s1, m);
                s2 += __shfl_xor_sync(0xffffffffu, s2, m);
            }
            const float mu  = s1 * (1.0f / HID);
            const float var = s2 * (1.0f / HID) - mu * mu;
            const float rs  = rsqrtf(var + 1e-5f);
            const float4 gg = reinterpret_cast<const float4*>(g1s)[lane];
            const float4 ee = reinterpret_cast<const float4*>(be1s)[lane];
            float h0 = gelu_fast((v[0] - mu) * rs * gg.x + ee.x);
            float h1 = gelu_fast((v[1] - mu) * rs * gg.y + ee.y);
            float h2 = gelu_fast((v[2] - mu) * rs * gg.z + ee.z);
            float h3 = gelu_fast((v[3] - mu) * rs * gg.w + ee.w);
            __half2 p0 = __floats2half2_rn(h0, h1);
            __half2 p1 = __floats2half2_rn(h2, h3);
            uint2 pk;
            pk.x = *reinterpret_cast<uint32_t*>(&p0);
            pk.y = *reinterpret_cast<uint32_t*>(&p1);
            *dstp = pk;
        } else {
            uint2 z = {0u, 0u};
            *dstp = z;
        }
    }
    __syncthreads();

    // ---------------- Phase 2: HMMA m16n8k16, warp computes 16 rows x 64 cols
    const int r0  = wid * 16;
    const int gid = lane >> 2, tig = lane & 3;

    float acc[8][4];
    #pragma unroll
    for (int nt = 0; nt < 8; ++nt)
        #pragma unroll
        for (int j = 0; j < 4; ++j) acc[nt][j] = 0.0f;

    #pragma unroll
    for (int kt = 0; kt < 8; ++kt) {
        const int k0 = kt * 16;
        const uint32_t* arow0 = (const uint32_t*)(As + (r0 + gid) * APITCH + k0);
        const uint32_t* arow8 = (const uint32_t*)(As + (r0 + gid + 8) * APITCH + k0);
        uint32_t a0 = arow0[tig];
        uint32_t a1 = arow8[tig];
        uint32_t a2 = arow0[tig + 4];
        uint32_t a3 = arow8[tig + 4];
        #pragma unroll
        for (int nt = 0; nt < 8; ++nt) {
            const uint32_t* brow = (const uint32_t*)(Bs + (nt * 8 + gid) * APITCH + k0);
            uint32_t bb0 = brow[tig];
            uint32_t bb1 = brow[tig + 4];
            asm volatile(
                "mma.sync.aligned.m16n8k16.row.col.f32.f16.f16.f32 "
                "{%0,%1,%2,%3}, {%4,%5,%6,%7}, {%8,%9}, {%0,%1,%2,%3};"
                : "+f"(acc[nt][0]), "+f"(acc[nt][1]), "+f"(acc[nt][2]), "+f"(acc[nt][3])
                : "r"(a0), "r"(a1), "r"(a2), "r"(a3), "r"(bb0), "r"(bb1));
        }
    }

    // ---------------- Phase 3: +b2 ; LN(64) ; GELU ; dot(W3)+b3 ------------
    float zA[16], zB[16];
    float s1a = 0.f, s2a = 0.f, s1b = 0.f, s2b = 0.f;
    #pragma unroll
    for (int nt = 0; nt < 8; ++nt) {
        #pragma unroll
        for (int j = 0; j < 2; ++j) {
            const int col = nt * 8 + 2 * tig + j;
            const float bb = b2s[col];
            const float tA = acc[nt][j]     + bb;
            const float tB = acc[nt][2 + j] + bb;
            zA[nt * 2 + j] = tA;
            zB[nt * 2 + j] = tB;
            s1a += tA; s2a += tA * tA;
            s1b += tB; s2b += tB * tB;
        }
    }
    #pragma unroll
    for (int m = 1; m <= 2; m <<= 1) {
        s1a += __shfl_xor_sync(0xffffffffu, s1a, m);
        s2a += __shfl_xor_sync(0xffffffffu, s2a, m);
        s1b += __shfl_xor_sync(0xffffffffu, s1b, m);
        s2b += __shfl_xor_sync(0xffffffffu, s2b, m);
    }
    const float muA = s1a * (1.0f / HID2);
    const float rsA = rsqrtf(s2a * (1.0f / HID2) - muA * muA + 1e-5f);
    const float muB = s1b * (1.0f / HID2);
    const float rsB = rsqrtf(s2b * (1.0f / HID2) - muB * muB + 1e-5f);

    float dotA = 0.f, dotB = 0.f;
    #pragma unroll
    for (int nt = 0; nt < 8; ++nt) {
        #pragma unroll
        for (int j = 0; j < 2; ++j) {
            const int col = nt * 8 + 2 * tig + j;
            const float gg = g2s[col], be = be2s[col], ww = w3s[col];
            dotA = fmaf(gelu_fast((zA[nt*2+j] - muA) * rsA * gg + be), ww, dotA);
            dotB = fmaf(gelu_fast((zB[nt*2+j] - muB) * rsB * gg + be), ww, dotB);
        }
    }
    #pragma unroll
    for (int m = 1; m <= 2; m <<= 1) {
        dotA += __shfl_xor_sync(0xffffffffu, dotA, m);
        dotB += __shfl_xor_sync(0xffffffffu, dotB, m);
    }

    if (tig == 0) {
        const float b3v = b3[0];
        const int eA = e0 + r0 + gid;
        const int eB = eA + 8;
        if (eA < E) out[eA] = dotA + b3v;
        if (eB < E) out[eB] = dotB + b3v;
    }
}

// ---------------------------------------------------------------------------
extern "C" void kernel_launch(void* const* d_in, const int* in_sizes, int n_in,
                              void* d_out, int out_size)
{
    const float* drug = (const float*)d_in[0];
    const float* dis  = (const float*)d_in[1];
    const int*   src  = (const int*)  d_in[2];
    const int*   dst  = (const int*)  d_in[3];
    const float* W1   = (const float*)d_in[4];
    const float* b1   = (const float*)d_in[5];
    const float* g1   = (const float*)d_in[6];
    const float* be1  = (const float*)d_in[7];
    const float* W2   = (const float*)d_in[8];
    const float* b2   = (const float*)d_in[9];
    const float* g2   = (const float*)d_in[10];
    const float* be2  = (const float*)d_in[11];
    const float* W3   = (const float*)d_in[12];
    const float* b3   = (const float*)d_in[13];
    float* out = (float*)d_out;

    const int n_drug = in_sizes[0] / FEAT;
    const int n_dis  = in_sizes[1] / FEAT;
    const int E      = in_sizes[2];

    const int nmax = n_drug > n_dis ? n_drug : n_dis;
    dim3 pgrid((nmax + 31) / 32, 2);
    precompute_kernel<<<pgrid, THREADS>>>(drug, dis, W1, n_drug, n_dis);

    cudaFuncSetAttribute(edge_kernel, cudaFuncAttributeMaxDynamicSharedMemorySize, SM_TOTAL);
    const int blocks = (E + BM - 1) / BM;
    edge_kernel<<<blocks, THREADS, SM_TOTAL>>>(
        src, dst, b1, g1, be1, W2, b2, g2, be2, W3, b3, out, E);
}